// round 5
// baseline (speedup 1.0000x reference)
#include <cuda_runtime.h>
#include <cuda_bf16.h>
#include <stdint.h>

// Problem constants: shape (16, 1, 320, 320) fp32, two tensors (pred, target)
#define NIMG   16
#define H      320
#define W      320
#define W2     160             // uint2 pairs per row
#define WPR    10              // 32-bit words per row (320/32)
#define NPIX   (NIMG * H * W)  // 1,638,400
#define NROWS  (NIMG * H)      // 5,120
#define SENT   0x7FFF
#define SENT2  (SENT * SENT)
#define BIGF   1e12f
#define NB_LOSS (NPIX / 512)   // 3200 blocks, 2 pixels per thread

// Scratch (static device globals — no allocation).
// g_D[p]: low16  = tensor0:  class<<15 | horizDistToOppositeClass
//         high16 = tensor1:  class<<15 | horizDistToOppositeClass
__device__ __align__(256) uint32_t g_D[NPIX];
__device__ double       g_part[NB_LOSS];
__device__ unsigned int g_ticket = 0;   // self-resetting via atomicInc wrap

// ---------------------------------------------------------------------------
// Horizontal distance (including self) to the nearest bit of the class
// selected by pol (pol=0 -> set bits, pol=~0 -> clear bits). wrow in smem.
__device__ __forceinline__ int nearest_dist(const uint32_t* wrow, int k, int o,
                                            uint32_t pol) {
    uint32_t c = wrow[k] ^ pol;
    int dl = SENT, dr = SENT;
    uint32_t low = c & (uint32_t)((2ull << o) - 1ull);      // bits [0..o]
    if (low) {
        dl = o - (31 - __clz(low));
    } else {
        for (int k2 = k - 1; k2 >= 0; --k2) {
            uint32_t mm = wrow[k2] ^ pol;
            if (mm) { dl = o + 32 * (k - k2) - (31 - __clz(mm)); break; }
        }
    }
    uint32_t high = c & (uint32_t)(0xFFFFFFFFull << o);     // bits [o..31]
    if (high) {
        dr = (__ffs(high) - 1) - o;
    } else {
        for (int k2 = k + 1; k2 < WPR; ++k2) {
            uint32_t mm = wrow[k2] ^ pol;
            if (mm) { dr = 32 * (k2 - k) - o + (__ffs(mm) - 1); break; }
        }
    }
    return min(min(dl, dr), SENT);
}

// ---------------------------------------------------------------------------
// Kernel A: fused threshold+pack (smem ballots) + horizontal pass for BOTH
// tensors. Two image rows per block; 640 threads.
__global__ void __launch_bounds__(640) k_rows(const float* __restrict__ pred,
                                              const float* __restrict__ targ) {
    int x = threadIdx.x;                   // 0..639
    int rowsel = (x >= W) ? 1 : 0;
    int xx = x - rowsel * W;               // 0..319
    int r = blockIdx.x * 2 + rowsel;       // global row
    int base = r * W;

    __shared__ uint32_t wrow[2][2][WPR];   // [tensor][rowsel][word]
    int k = xx >> 5, o = xx & 31;

    float p = pred[base + xx];
    float t = targ[base + xx];
    unsigned bp = __ballot_sync(0xFFFFFFFFu, p > 0.5f);
    unsigned bt = __ballot_sync(0xFFFFFFFFu, t > 0.5f);
    if (o == 0) { wrow[0][rowsel][k] = bp; wrow[1][rowsel][k] = bt; }
    __syncthreads();

    const uint32_t* w0 = wrow[0][rowsel];
    const uint32_t* w1 = wrow[1][rowsel];
    uint32_t c0 = (w0[k] >> o) & 1u;
    uint32_t c1 = (w1[k] >> o) & 1u;
    int d0 = nearest_dist(w0, k, o, c0 ? 0xFFFFFFFFu : 0u);
    int d1 = nearest_dist(w1, k, o, c1 ? 0xFFFFFFFFu : 0u);

    g_D[base + xx] = (c0 << 15) | (uint32_t)d0 | (c1 << 31) | ((uint32_t)d1 << 16);
}

// ---------------------------------------------------------------------------
// Update the 4 running bests from one neighbor-row pair value.
__device__ __forceinline__ void upd4(uint2 v, int dy2,
                                     uint32_t m00, uint32_t m01,
                                     uint32_t m10, uint32_t m11,
                                     int& b00, int& b01, int& b10, int& b11) {
    uint32_t xa;
    xa = (v.x & 0xFFFFu) ^ m00; { int a = (xa < 0x8000u) ? (int)xa : 0; b00 = min(b00, dy2 + a * a); }
    xa = (v.x >> 16)     ^ m01; { int a = (xa < 0x8000u) ? (int)xa : 0; b01 = min(b01, dy2 + a * a); }
    xa = (v.y & 0xFFFFu) ^ m10; { int a = (xa < 0x8000u) ? (int)xa : 0; b10 = min(b10, dy2 + a * a); }
    xa = (v.y >> 16)     ^ m11; { int a = (xa < 0x8000u) ? (int)xa : 0; b11 = min(b11, dy2 + a * a); }
}

// ---------------------------------------------------------------------------
// Kernel B: vertical envelope (chunked, exact early-exit) + loss + reduction.
// Each thread owns 2 adjacent pixels (one uint2 of g_D). y is warp-uniform
// (160 pairs per row = 5 warps per row), so bounds checks don't diverge.
__global__ void __launch_bounds__(256) k_loss(const float* __restrict__ pred,
                                              const float* __restrict__ targ,
                                              float* __restrict__ out) {
    int i = blockIdx.x * blockDim.x + threadIdx.x;     // pair index
    int y = (i / W2) % H;

    const uint2* D2 = (const uint2*)g_D;
    uint2 own = D2[i];

    uint32_t m00 = own.x & 0x8000u;          // class bits, in place
    uint32_t m01 = (own.x >> 16) & 0x8000u;
    uint32_t m10 = own.y & 0x8000u;
    uint32_t m11 = (own.y >> 16) & 0x8000u;
    int d;
    d = (int)(own.x & 0x7FFFu);         int b00 = d * d;
    d = (int)((own.x >> 16) & 0x7FFFu); int b01 = d * d;
    d = (int)(own.y & 0x7FFFu);         int b10 = d * d;
    d = (int)((own.y >> 16) & 0x7FFFu); int b11 = d * d;

    // issue input loads early (independent of the loop)
    float2 pv = ((const float2*)pred)[i];
    float2 tv = ((const float2*)targ)[i];

    int bb = max(max(b00, b01), max(b10, b11));
    for (int dy0 = 1; dy0 < H; dy0 += 4) {
        if (dy0 * dy0 >= bb) break;
#pragma unroll
        for (int j = 0; j < 4; ++j) {
            int dy = dy0 + j;
            int dy2 = dy * dy;
            if (y >= dy) {
                uint2 v = D2[i - dy * W2];
                upd4(v, dy2, m00, m01, m10, m11, b00, b01, b10, b11);
            }
            if (y + dy < H) {
                uint2 v = D2[i + dy * W2];
                upd4(v, dy2, m00, m01, m10, m11, b00, b01, b10, b11);
            }
        }
        bb = max(max(b00, b01), max(b10, b11));
    }

    // Saturation: best>=SENT^2 means NO opposite-class pixel in the image.
    //   fg pixel (class bit set), no bg anywhere -> field^2 = BIG
    //   bg pixel, no fg anywhere -> reference zeroes the whole field -> 0
    float f00 = (b00 >= SENT2) ? (m00 ? BIGF : 0.f) : (float)b00;
    float f01 = (b01 >= SENT2) ? (m01 ? BIGF : 0.f) : (float)b01;
    float f10 = (b10 >= SENT2) ? (m10 ? BIGF : 0.f) : (float)b10;
    float f11 = (b11 >= SENT2) ? (m11 ? BIGF : 0.f) : (float)b11;

    float e0 = pv.x - tv.x;
    float e1 = pv.y - tv.y;
    float term = e0 * e0 * (f00 + f01) + e1 * e1 * (f10 + f11);

    // block reduce (float) -> double partial
#pragma unroll
    for (int off = 16; off; off >>= 1)
        term += __shfl_down_sync(0xFFFFFFFFu, term, off);
    __shared__ float ws[8];
    if ((threadIdx.x & 31) == 0) ws[threadIdx.x >> 5] = term;
    __syncthreads();
    __shared__ bool isLast;
    if (threadIdx.x == 0) {
        float v = ws[0];
#pragma unroll
        for (int k = 1; k < 8; ++k) v += ws[k];
        g_part[blockIdx.x] = (double)v;
        __threadfence();
        unsigned int tk = atomicInc(&g_ticket, NB_LOSS - 1);  // wraps to 0 => self-reset
        isLast = (tk == NB_LOSS - 1);
    }
    __syncthreads();

    if (isLast) {
        double acc = 0.0;
        for (int k = threadIdx.x; k < NB_LOSS; k += 256) acc += g_part[k];
#pragma unroll
        for (int off = 16; off; off >>= 1)
            acc += __shfl_down_sync(0xFFFFFFFFu, acc, off);
        __shared__ double wd[8];
        if ((threadIdx.x & 31) == 0) wd[threadIdx.x >> 5] = acc;
        __syncthreads();
        if (threadIdx.x == 0) {
            double s = wd[0];
#pragma unroll
            for (int k = 1; k < 8; ++k) s += wd[k];
            out[0] = (float)(s / (double)NPIX);
        }
    }
}

// ---------------------------------------------------------------------------
extern "C" void kernel_launch(void* const* d_in, const int* in_sizes, int n_in,
                              void* d_out, int out_size) {
    const float* pred = (const float*)d_in[0];
    const float* targ = (const float*)d_in[1];
    float* out = (float*)d_out;

    k_rows<<<NROWS / 2, 640>>>(pred, targ);
    k_loss<<<NB_LOSS, 256>>>(pred, targ, out);
}

// round 6
// speedup vs baseline: 1.1246x; 1.1246x over previous
#include <cuda_runtime.h>
#include <cuda_bf16.h>
#include <stdint.h>

// Problem constants: shape (16, 1, 320, 320) fp32, two tensors (pred, target)
#define NIMG   16
#define H      320
#define W      320
#define W2     160             // uint2 pairs per row
#define WPR    10              // 32-bit words per row (320/32)
#define NPIX   (NIMG * H * W)  // 1,638,400
#define NROWS  (NIMG * H)      // 5,120
#define SENT   0x7FFF
#define SENT2  (SENT * SENT)
#define BIGF   1e12f
#define GRID   888             // 148 SMs * 6 blocks (co-residency forced by launch_bounds)
#define NTILE  (NPIX / 512)    // 3200 pair-tiles of 256 threads

// Scratch (static device globals — no allocation).
// g_D[p]: low16  = tensor0:  class<<15 | horizDistToOppositeClass
//         high16 = tensor1:  class<<15 | horizDistToOppositeClass
__device__ __align__(256) uint32_t g_D[NPIX];
__device__ double            g_part[GRID];
__device__ unsigned          g_cnt0 = 0, g_cnt1 = 0;       // self-reset via atomicInc wrap
__device__ volatile unsigned g_sense0 = 0, g_sense1 = 0;   // flips once per launch

// ---------------------------------------------------------------------------
// Horizontal distance (incl. self) to nearest bit of class selected by pol
// (pol=0 -> set bits, pol=~0 -> clear bits). wr = 10 row words in smem,
// wk = word k value (register). Exact; far-scan loops are rare on random data.
__device__ __forceinline__ int nearest_dist(const uint32_t* wr, uint32_t wk,
                                            int k, int o, uint32_t pol) {
    uint32_t c = wk ^ pol;
    int dl = SENT, dr = SENT;
    uint32_t low = c & (uint32_t)((2ull << o) - 1ull);      // bits [0..o]
    if (low) {
        dl = o - (31 - __clz(low));
    } else {
        for (int k2 = k - 1; k2 >= 0; --k2) {
            uint32_t mm = wr[k2] ^ pol;
            if (mm) { dl = o + 32 * (k - k2) - (31 - __clz(mm)); break; }
        }
    }
    uint32_t high = c & (uint32_t)(0xFFFFFFFFull << o);     // bits [o..31]
    if (high) {
        dr = (__ffs(high) - 1) - o;
    } else {
        for (int k2 = k + 1; k2 < WPR; ++k2) {
            uint32_t mm = wr[k2] ^ pol;
            if (mm) { dr = 32 * (k2 - k) - o + (__ffs(mm) - 1); break; }
        }
    }
    return min(min(dl, dr), SENT);
}

// ---------------------------------------------------------------------------
// Packed neighbor update: v = packed field word, m = query class mask
// (0x8000-bits where query pixel is fg, per tensor halfword).
// a = __vmaxs2(v ^ m, 0): same class -> d, opposite class -> 0 (exact).
__device__ __forceinline__ void upd2(uint32_t v, uint32_t m, int dy2,
                                     int& b0, int& b1) {
    uint32_t a = __vmaxs2(v ^ m, 0u);
    int a0 = (int)(a & 0xFFFFu);
    int a1 = (int)(a >> 16);
    b0 = min(b0, a0 * a0 + dy2);
    b1 = min(b1, a1 * a1 + dy2);
}

// ---------------------------------------------------------------------------
__global__ void __launch_bounds__(256, 6)
k_fused(const float* __restrict__ pred, const float* __restrict__ targ,
        float* __restrict__ out) {
    const int tid  = threadIdx.x;
    const int bid  = blockIdx.x;
    const int warp = tid >> 5;
    const int L    = tid & 31;

    // Read barrier senses BEFORE any work (flip happens only after all blocks
    // arrive, i.e. after every block has executed this line).
    const unsigned s0 = g_sense0;
    const unsigned s1 = g_sense1;

    __shared__ uint32_t srow[8][2][WPR];    // per-warp row bit-words

    // ---------------- Phase A: horizontal pass, one warp per row ----------
    int row = bid * 8 + warp;               // 888*8 = 7104 >= 5120 rows
    if (row < NROWS) {
        int base = row * W;
        uint32_t* sp = &srow[warp][0][0];
        uint32_t* st = &srow[warp][1][0];
        for (int j = 0; j < WPR; ++j) {
            float p = pred[base + j * 32 + L];
            float t = targ[base + j * 32 + L];
            uint32_t bp = __ballot_sync(0xFFFFFFFFu, p > 0.5f);
            uint32_t bt = __ballot_sync(0xFFFFFFFFu, t > 0.5f);
            if (L == 0) { sp[j] = bp; st[j] = bt; }
        }
        __syncwarp();
        for (int j = 0; j < WPR; ++j) {
            uint32_t w0 = sp[j], w1 = st[j];
            uint32_t c0 = (w0 >> L) & 1u;
            uint32_t c1 = (w1 >> L) & 1u;
            int d0 = nearest_dist(sp, w0, j, L, c0 ? 0xFFFFFFFFu : 0u);
            int d1 = nearest_dist(st, w1, j, L, c1 ? 0xFFFFFFFFu : 0u);
            g_D[base + j * 32 + L] =
                (c0 << 15) | (uint32_t)d0 | (c1 << 31) | ((uint32_t)d1 << 16);
        }
    }

    // ---------------- Grid barrier #1 (sense-reversing, self-resetting) ---
    __syncthreads();
    if (tid == 0) {
        __threadfence();
        unsigned t = atomicInc(&g_cnt0, GRID - 1);
        if (t == GRID - 1) g_sense0 = s0 ^ 1u;
        else while (g_sense0 == s0) __nanosleep(32);
        __threadfence();
    }
    __syncthreads();

    // ---------------- Phase B: vertical envelope + loss -------------------
    const uint2* D2 = (const uint2*)g_D;
    float fsum = 0.f;

    for (int tile = bid; tile < NTILE; tile += GRID) {
        int i = tile * 256 + tid;           // pair index (2 horiz pixels)
        int r = i / W2;
        int y = r % H;

        uint2 own = D2[i];
        uint32_t mx = own.x & 0x80008000u;  // query class masks, in place
        uint32_t my = own.y & 0x80008000u;
        int d;
        d = (int)(own.x & 0x7FFFu);         int b00 = d * d;
        d = (int)((own.x >> 16) & 0x7FFFu); int b01 = d * d;
        d = (int)(own.y & 0x7FFFu);         int b10 = d * d;
        d = (int)((own.y >> 16) & 0x7FFFu); int b11 = d * d;

        float2 pv = ((const float2*)pred)[i];
        float2 tv = ((const float2*)targ)[i];

        int bb = max(max(b00, b01), max(b10, b11));
        for (int dy = 1; dy < H; dy += 2) {     // chunks of 2 dy steps
            if (dy * dy >= bb) break;
            int dy2a = dy * dy;
            int dyb  = dy + 1;
            int dy2b = dyb * dyb;
            const uint2* pu = D2 + (i - dy * W2);
            const uint2* pd = D2 + (i + dy * W2);
            if (y >= dy) {
                uint2 v = pu[0];
                upd2(v.x, mx, dy2a, b00, b01);
                upd2(v.y, my, dy2a, b10, b11);
            }
            if (y + dy < H) {
                uint2 v = pd[0];
                upd2(v.x, mx, dy2a, b00, b01);
                upd2(v.y, my, dy2a, b10, b11);
            }
            if (y >= dyb) {
                uint2 v = pu[-W2];
                upd2(v.x, mx, dy2b, b00, b01);
                upd2(v.y, my, dy2b, b10, b11);
            }
            if (y + dyb < H) {
                uint2 v = pd[W2];
                upd2(v.x, mx, dy2b, b00, b01);
                upd2(v.y, my, dy2b, b10, b11);
            }
            bb = max(max(b00, b01), max(b10, b11));
        }

        // Saturation: best>=SENT^2 <=> no opposite-class pixel in the image.
        //   fg pixel, no bg anywhere -> field^2 = BIG
        //   bg pixel, no fg anywhere -> reference zeroes the field -> 0
        float f00 = (b00 >= SENT2) ? ((mx & 0x8000u) ? BIGF : 0.f) : (float)b00;
        float f01 = (b01 >= SENT2) ? ((mx >> 16)     ? BIGF : 0.f) : (float)b01;
        float f10 = (b10 >= SENT2) ? ((my & 0x8000u) ? BIGF : 0.f) : (float)b10;
        float f11 = (b11 >= SENT2) ? ((my >> 16)     ? BIGF : 0.f) : (float)b11;

        float e0 = pv.x - tv.x;
        float e1 = pv.y - tv.y;
        fsum += e0 * e0 * (f00 + f01) + e1 * e1 * (f10 + f11);
    }

    // block reduce fsum -> double partial
#pragma unroll
    for (int off = 16; off; off >>= 1)
        fsum += __shfl_down_sync(0xFFFFFFFFu, fsum, off);
    __shared__ float ws[8];
    if (L == 0) ws[warp] = fsum;
    __syncthreads();
    if (tid == 0) {
        float v = ws[0];
#pragma unroll
        for (int k = 1; k < 8; ++k) v += ws[k];
        g_part[bid] = (double)v;
    }

    // ---------------- Grid barrier #2 -------------------------------------
    __syncthreads();
    if (tid == 0) {
        __threadfence();
        unsigned t = atomicInc(&g_cnt1, GRID - 1);
        if (t == GRID - 1) g_sense1 = s1 ^ 1u;
        else while (g_sense1 == s1) __nanosleep(32);
        __threadfence();
    }
    __syncthreads();

    // ---------------- Final reduction by block 0 ---------------------------
    if (bid == 0) {
        double acc = 0.0;
        for (int k = tid; k < GRID; k += 256) acc += g_part[k];
#pragma unroll
        for (int off = 16; off; off >>= 1)
            acc += __shfl_down_sync(0xFFFFFFFFu, acc, off);
        __shared__ double wd[8];
        if (L == 0) wd[warp] = acc;
        __syncthreads();
        if (tid == 0) {
            double s = wd[0];
#pragma unroll
            for (int k = 1; k < 8; ++k) s += wd[k];
            out[0] = (float)(s / (double)NPIX);
        }
    }
}

// ---------------------------------------------------------------------------
extern "C" void kernel_launch(void* const* d_in, const int* in_sizes, int n_in,
                              void* d_out, int out_size) {
    const float* pred = (const float*)d_in[0];
    const float* targ = (const float*)d_in[1];
    float* out = (float*)d_out;

    k_fused<<<GRID, 256>>>(pred, targ, out);
}

// round 7
// speedup vs baseline: 1.1495x; 1.0222x over previous
#include <cuda_runtime.h>
#include <cuda_bf16.h>
#include <stdint.h>

// Problem constants: shape (16, 1, 320, 320) fp32, two tensors (pred, target)
#define NIMG   16
#define H      320
#define W      320
#define W2     160             // pixel-pairs per row
#define WPR    10              // 32-bit words per row (320/32)
#define NPIX   (NIMG * H * W)  // 1,638,400
#define NROWS  (NIMG * H)      // 5,120
#define SENT   0x7FFF
#define SENT2  (SENT * SENT)
#define CAPQ   0x3FFF          // saturation cap for stored squared distances
#define BIGF   1e12f
#define GRID   888             // 148 SMs * 6 blocks (co-residency via launch_bounds)
#define NTILE  (NPIX / 512)    // 3200 pair-tiles of 256 threads

// Scratch (static device globals — no allocation).
// g_D  [p]: per tensor halfword: class<<15 | exact horiz dist to opposite class
// g_Dsq[p]: per tensor halfword: class<<15 | min(dist^2, CAPQ)
__device__ __align__(256) uint32_t g_D[NPIX];
__device__ __align__(256) uint32_t g_Dsq[NPIX];
__device__ double            g_part[GRID];
__device__ unsigned          g_cnt0 = 0, g_cnt1 = 0;       // self-reset via atomicInc wrap
__device__ volatile unsigned g_sense0 = 0, g_sense1 = 0;   // flips once per launch

// ---------------------------------------------------------------------------
// Exact horizontal distance to nearest opposite-class bit, branchless 64-bit
// window for d<=32 (the overwhelmingly common case), rare multi-word scan
// fallback for larger d. wr = 10 row bit-words in smem, pol flips class.
__device__ __forceinline__ int nearest_dist64(const uint32_t* wr, int j, int L,
                                              uint32_t pol) {
    uint32_t cj   = wr[j] ^ pol;
    uint32_t cjm1 = (j > 0)       ? (wr[j - 1] ^ pol) : 0u;
    uint32_t cjp1 = (j < WPR - 1) ? (wr[j + 1] ^ pol) : 0u;

    // left: bits [x-32 .. x] in a 64-bit window, bit position 32+L
    uint64_t winL = ((uint64_t)cj << 32) | cjm1;
    int pos = 32 + L;
    uint64_t mlow = winL & ((2ull << pos) - 1ull);     // pos=63 wraps to all-ones
    int dl;
    if (mlow) {
        dl = pos - 63 + __clzll((long long)mlow);
    } else {
        dl = SENT;
        for (int k2 = j - 2; k2 >= 0; --k2) {          // rare
            uint32_t mm = wr[k2] ^ pol;
            if (mm) { dl = j * 32 + L - (k2 * 32 + 31 - __clz(mm)); break; }
        }
    }
    // right: bits [x .. x+63-L], window of words j, j+1, bit position L
    uint64_t winR = ((uint64_t)cjp1 << 32) | cj;
    uint64_t mhigh = winR & (~0ull << L);              // self bit never set in c
    int dr;
    if (mhigh) {
        dr = __ffsll((long long)mhigh) - 1 - L;
    } else {
        dr = SENT;
        for (int k2 = j + 2; k2 < WPR; ++k2) {         // rare
            uint32_t mm = wr[k2] ^ pol;
            if (mm) { dr = k2 * 32 + (__ffs(mm) - 1) - (j * 32 + L); break; }
        }
    }
    return min(min(dl, dr), SENT);
}

// ---------------------------------------------------------------------------
// Exact per-pixel fallback (cold; runs only when the SIMD result saturated,
// i.e. the true field value may exceed CAPQ). Reads exact g_D.
__device__ __noinline__ float fallback_pixel(int idx, int y) {
    uint32_t own = g_D[idx];
    uint32_t c0 = (own >> 15) & 1u;
    uint32_t c1 = (own >> 31) & 1u;
    int d;
    d = (int)(own & 0x7FFFu);         int b0 = d * d;
    d = (int)((own >> 16) & 0x7FFFu); int b1 = d * d;
    for (int dy = 1; dy < H; ++dy) {
        int dy2 = dy * dy;
        if (dy2 >= b0 && dy2 >= b1) break;
        if (y >= dy) {
            uint32_t v = g_D[idx - dy * W];
            int a0 = (((v >> 15) & 1u) == c0) ? (int)(v & 0x7FFFu) : 0;
            int a1 = (((v >> 31) & 1u) == c1) ? (int)((v >> 16) & 0x7FFFu) : 0;
            b0 = min(b0, dy2 + a0 * a0);
            b1 = min(b1, dy2 + a1 * a1);
        }
        if (y + dy < H) {
            uint32_t v = g_D[idx + dy * W];
            int a0 = (((v >> 15) & 1u) == c0) ? (int)(v & 0x7FFFu) : 0;
            int a1 = (((v >> 31) & 1u) == c1) ? (int)((v >> 16) & 0x7FFFu) : 0;
            b0 = min(b0, dy2 + a0 * a0);
            b1 = min(b1, dy2 + a1 * a1);
        }
    }
    // best>=SENT2 <=> no opposite-class pixel anywhere in the image:
    //   fg pixel -> field^2 = BIG ; bg pixel -> reference zeroes field -> 0
    float f0 = (b0 >= SENT2) ? (c0 ? BIGF : 0.f) : (float)b0;
    float f1 = (b1 >= SENT2) ? (c1 ? BIGF : 0.f) : (float)b1;
    return f0 + f1;
}

// ---------------------------------------------------------------------------
// Hot SIMD neighbor update: 4 ops per packed word.
__device__ __forceinline__ void updq(uint2 v, uint32_t mx, uint32_t my,
                                     uint32_t dp, uint32_t& bx, uint32_t& by) {
    bx = __vmins2(bx, __vadd2(__vmaxs2(v.x ^ mx, 0u), dp));
    by = __vmins2(by, __vadd2(__vmaxs2(v.y ^ my, 0u), dp));
}

// ---------------------------------------------------------------------------
__global__ void __launch_bounds__(256, 6)
k_fused(const float* __restrict__ pred, const float* __restrict__ targ,
        float* __restrict__ out) {
    const int tid  = threadIdx.x;
    const int bid  = blockIdx.x;
    const int warp = tid >> 5;
    const int L    = tid & 31;

    // Read barrier senses BEFORE any work.
    const unsigned s0 = g_sense0;
    const unsigned s1 = g_sense1;

    __shared__ uint32_t srow[8][2][WPR];

    // ---------------- Phase A: horizontal pass, one warp per row ----------
    int row = bid * 8 + warp;               // 888*8 = 7104 >= 5120 rows
    if (row < NROWS) {
        int base = row * W;
        uint32_t* sp = &srow[warp][0][0];
        uint32_t* st = &srow[warp][1][0];
        for (int j = 0; j < WPR; ++j) {
            float p = pred[base + j * 32 + L];
            float t = targ[base + j * 32 + L];
            uint32_t bp = __ballot_sync(0xFFFFFFFFu, p > 0.5f);
            uint32_t bt = __ballot_sync(0xFFFFFFFFu, t > 0.5f);
            if (L == 0) { sp[j] = bp; st[j] = bt; }
        }
        __syncwarp();
        for (int j = 0; j < WPR; ++j) {
            uint32_t c0 = (sp[j] >> L) & 1u;
            uint32_t c1 = (st[j] >> L) & 1u;
            int d0 = nearest_dist64(sp, j, L, c0 ? 0xFFFFFFFFu : 0u);
            int d1 = nearest_dist64(st, j, L, c1 ? 0xFFFFFFFFu : 0u);
            int pix = base + j * 32 + L;
            g_D[pix] = (c0 << 15) | (uint32_t)d0 | (c1 << 31) | ((uint32_t)d1 << 16);
            uint32_t q0 = (c0 << 15) | (uint32_t)min(d0 * d0, CAPQ);
            uint32_t q1 = (c1 << 15) | (uint32_t)min(d1 * d1, CAPQ);
            g_Dsq[pix] = q0 | (q1 << 16);
        }
    }

    // ---------------- Grid barrier #1 (sense-reversing, self-resetting) ---
    __syncthreads();
    if (tid == 0) {
        __threadfence();
        unsigned t = atomicInc(&g_cnt0, GRID - 1);
        if (t == GRID - 1) g_sense0 = s0 ^ 1u;
        else while (g_sense0 == s0) __nanosleep(32);
        __threadfence();
    }
    __syncthreads();

    // ---------------- Phase B: SIMD vertical envelope + loss --------------
    const uint2* DQ = (const uint2*)g_Dsq;
    float fsum = 0.f;

    for (int tile = bid; tile < NTILE; tile += GRID) {
        int i = tile * 256 + tid;           // pair index (2 horiz pixels)
        int y = (i / W2) % H;               // warp-uniform (160 % 32 == 0)

        uint2 own = DQ[i];
        uint32_t mx = own.x & 0x80008000u;  // query class masks
        uint32_t my = own.y & 0x80008000u;
        uint32_t bx = __vmaxs2(own.x ^ mx, 0u);   // own sat d^2 (<= CAPQ)
        uint32_t by = __vmaxs2(own.y ^ my, 0u);

        float2 pv = ((const float2*)pred)[i];
        float2 tv = ((const float2*)targ)[i];

        // chunks of 2 dy steps; first chunk unconditional (never exits before)
        int dy = 1;
        do {
            int dy2a = dy * dy;
            int dy2b = (dy + 1) * (dy + 1);
            uint32_t dpa = (uint32_t)dy2a * 0x00010001u;
            uint32_t dpb = (uint32_t)dy2b * 0x00010001u;
            const uint2* pu = DQ + (i - dy * W2);
            const uint2* pd = DQ + (i + dy * W2);
            if (y >= dy)          updq(pu[0],   mx, my, dpa, bx, by);
            if (y + dy < H)       updq(pd[0],   mx, my, dpa, bx, by);
            if (y >= dy + 1)      updq(pu[-W2], mx, my, dpb, bx, by);
            if (y + dy + 1 < H)   updq(pd[W2],  mx, my, dpb, bx, by);
            dy += 2;
            uint32_t m2 = __vmaxs2(bx, by);
            int bb = max((int)(m2 >> 16), (int)(m2 & 0xFFFFu));
            if (dy * dy >= bb) break;       // bb<=CAPQ => exits by dy<=128
        } while (true);

        int b00 = (int)(bx & 0xFFFFu), b01 = (int)(bx >> 16);
        int b10 = (int)(by & 0xFFFFu), b11 = (int)(by >> 16);

        float e0 = pv.x - tv.x;
        float e1 = pv.y - tv.y;
        // any field >= CAPQ may be saturated -> exact recompute (cold, ~never)
        float f0 = (max(b00, b01) >= CAPQ) ? fallback_pixel(2 * i, y)
                                           : (float)(b00 + b01);
        float f1 = (max(b10, b11) >= CAPQ) ? fallback_pixel(2 * i + 1, y)
                                           : (float)(b10 + b11);
        fsum += e0 * e0 * f0 + e1 * e1 * f1;
    }

    // block reduce fsum -> double partial
#pragma unroll
    for (int off = 16; off; off >>= 1)
        fsum += __shfl_down_sync(0xFFFFFFFFu, fsum, off);
    __shared__ float ws[8];
    if (L == 0) ws[warp] = fsum;
    __syncthreads();
    if (tid == 0) {
        float v = ws[0];
#pragma unroll
        for (int k = 1; k < 8; ++k) v += ws[k];
        g_part[bid] = (double)v;
    }

    // ---------------- Grid barrier #2 -------------------------------------
    __syncthreads();
    if (tid == 0) {
        __threadfence();
        unsigned t = atomicInc(&g_cnt1, GRID - 1);
        if (t == GRID - 1) g_sense1 = s1 ^ 1u;
        else while (g_sense1 == s1) __nanosleep(32);
        __threadfence();
    }
    __syncthreads();

    // ---------------- Final reduction by block 0 ---------------------------
    if (bid == 0) {
        double acc = 0.0;
        for (int k = tid; k < GRID; k += 256) acc += g_part[k];
#pragma unroll
        for (int off = 16; off; off >>= 1)
            acc += __shfl_down_sync(0xFFFFFFFFu, acc, off);
        __shared__ double wd[8];
        if (L == 0) wd[warp] = acc;
        __syncthreads();
        if (tid == 0) {
            double s = wd[0];
#pragma unroll
            for (int k = 1; k < 8; ++k) s += wd[k];
            out[0] = (float)(s / (double)NPIX);
        }
    }
}

// ---------------------------------------------------------------------------
extern "C" void kernel_launch(void* const* d_in, const int* in_sizes, int n_in,
                              void* d_out, int out_size) {
    const float* pred = (const float*)d_in[0];
    const float* targ = (const float*)d_in[1];
    float* out = (float*)d_out;

    k_fused<<<GRID, 256>>>(pred, targ, out);
}